// round 10
// baseline (speedup 1.0000x reference)
#include <cuda_runtime.h>
#include <cuda_fp16.h>
#include <stdint.h>
#include <math.h>

#define B_   64
#define A_   128
#define M_   8
#define D_   384
#define O0_  256
#define O2_  192
#define O4_  160

// smem pitches (bytes) for X buffers [b][k] fp16: K*2+16 (all ≡16 mod 128 -> LDSM conflict-free)
#define P0 784     // K=384
#define P1 528     // K=256
#define P2 400     // K=192

// per-CTA (256 threads, 32 batch rows) smem layout
#define X0_OFF  0                    // 32*784 = 25088
#define X1_OFF  25088                // 32*528 = 16896
#define RED_OFF 41984                // 32*8*4 = 1024
#define SMEM_BYTES 43008

#define NTHREADS 256

__device__ float g_partial[B_ * A_ * M_];

__device__ __forceinline__ float celu01(float x) {
    return x > 0.f ? x : 0.1f * expm1f(10.f * x);
}

__device__ __forceinline__ uint32_t smem_u32(const void* p) {
    uint32_t a;
    asm("{ .reg .u64 t; cvta.to.shared.u64 t, %1; cvt.u32.u64 %0, t; }" : "=r"(a) : "l"(p));
    return a;
}

// permuted X row byte offset (pair p -> phys pair (p>>1)+(p&1)*4 within 16-col groups):
// B-frag lane t carries logical k (4t,4t+1)/(4t+2,4t+3) -> W loads are contiguous float4.
__device__ __forceinline__ uint32_t permb(int k) {
    int p  = (k >> 1) & 7;
    int pp = (p >> 1) + ((p & 1) << 2);
    return (uint32_t)(((k & ~15) << 1) + (pp << 2) + ((k & 1) << 1));
}

__device__ __forceinline__ uint32_t cvt2h(float x, float y) {
    uint32_t r;
    asm("cvt.rn.f16x2.f32 %0, %1, %2;" : "=r"(r) : "f"(y), "f"(x));
    return r;
}
// W split: fp16 hi + fp16 residual lo (eff ~22 mantissa bits)
__device__ __forceinline__ void split2h(float x, float y, uint32_t& hi, uint32_t& lo) {
    hi = cvt2h(x, y);
    __half2 h = *reinterpret_cast<__half2*>(&hi);
    lo = cvt2h(x - __low2float(h), y - __high2float(h));
}

__device__ __forceinline__ void ldsm_x4(uint32_t& r0, uint32_t& r1, uint32_t& r2, uint32_t& r3,
                                        uint32_t addr) {
    asm volatile("ldmatrix.sync.aligned.m8n8.x4.shared.b16 {%0,%1,%2,%3}, [%4];"
                 : "=r"(r0), "=r"(r1), "=r"(r2), "=r"(r3) : "r"(addr));
}

__device__ __forceinline__ void mma16816(float c[4], const uint32_t a[4], const uint32_t b[2]) {
    asm volatile(
        "mma.sync.aligned.m16n8k16.row.col.f32.f16.f16.f32 "
        "{%0,%1,%2,%3}, {%4,%5,%6,%7}, {%8,%9}, {%0,%1,%2,%3};"
        : "+f"(c[0]), "+f"(c[1]), "+f"(c[2]), "+f"(c[3])
        : "r"(a[0]), "r"(a[1]), "r"(a[2]), "r"(a[3]), "r"(b[0]), "r"(b[1]));
}

// One layer: D[o][b] = celu(W[o][k] X[k][b] + bias) over this CTA's 32 batch rows.
// 8 warps; warp w owns m-tiles {w, w+8}∩[0,NMT) and all 4 n-tiles.
// W fp32 streamed (contiguous LDG.128, distance-2 parity prefetch), split to fp16
// hi/lo. B frags via ldsm.x4 (2 n-tiles per instr), software-pipelined one kc ahead.
// FINAL fuses the w6 dot: writes per-(b,warp) partials into red[].
template<int K, int O, int PIN, int POUT, bool FINAL>
__device__ __forceinline__ void layer(
    const float* __restrict__ Wg, const float* __restrict__ bias,
    const char* __restrict__ Xin, char* __restrict__ Yout,
    const float* __restrict__ w6p, float* __restrict__ red)
{
    const int lane  = threadIdx.x & 31;
    const int warp  = threadIdx.x >> 5;
    const int group = lane >> 2;
    const int tig   = lane & 3;
    constexpr int NMT = O / 16;
    constexpr int NK  = K / 16;
    const int nmt = (warp + 8 < NMT) ? 2 : 1;

    // B ldmatrix addresses: jj covers n-tiles 2jj,2jj+1.
    const int q = lane >> 3;
    const int rr = lane & 7;
    const uint32_t xbase = smem_u32(Xin);
    uint32_t aj[2];
#pragma unroll
    for (int jj = 0; jj < 2; jj++)
        aj[jj] = xbase + (uint32_t)((jj * 16 + (q >> 1) * 8 + rr) * PIN + (q & 1) * 16);

    float acc[2][4][4];
#pragma unroll
    for (int im = 0; im < 2; im++)
#pragma unroll
        for (int j = 0; j < 4; j++)
#pragma unroll
            for (int e = 0; e < 4; e++) acc[im][j][e] = 0.f;

    const float* wp0[2];
    const float* wp1[2];
#pragma unroll
    for (int im = 0; im < 2; im++) {
        wp0[im] = Wg + (size_t)((warp + im * 8) * 16 + group) * K + tig * 4;
        wp1[im] = wp0[im] + 8 * K;
    }

    // W parity double-buffers, prefetch distance 2
    float4 we0[2], we1[2], wo0[2], wo1[2];
#pragma unroll
    for (int im = 0; im < 2; im++) {
        if (im < nmt) {
            we0[im] = *(const float4*)(wp0[im]);
            we1[im] = *(const float4*)(wp1[im]);
            wo0[im] = *(const float4*)(wp0[im] + 16);
            wo1[im] = *(const float4*)(wp1[im] + 16);
        }
    }

    // B software pipeline: bb[parity][jj][4]
    uint32_t bb[2][2][4];
#pragma unroll
    for (int jj = 0; jj < 2; jj++)
        ldsm_x4(bb[0][jj][0], bb[0][jj][1], bb[0][jj][2], bb[0][jj][3], aj[jj]);

#pragma unroll 2
    for (int kc = 0; kc < NK; kc++) {
        const int p = kc & 1;
        const bool even = (p == 0);

        // split W chunk to fp16 hi/lo fragments
        uint32_t ah[2][4], al[2][4];
#pragma unroll
        for (int im = 0; im < 2; im++) {
            if (im < nmt) {
                float4 r0 = even ? we0[im] : wo0[im];
                float4 r1 = even ? we1[im] : wo1[im];
                split2h(r0.x, r0.y, ah[im][0], al[im][0]);
                split2h(r1.x, r1.y, ah[im][1], al[im][1]);
                split2h(r0.z, r0.w, ah[im][2], al[im][2]);
                split2h(r1.z, r1.w, ah[im][3], al[im][3]);
            }
        }

        // prefetch kc+1 B frags into the other parity
        if (kc + 1 < NK) {
#pragma unroll
            for (int jj = 0; jj < 2; jj++)
                ldsm_x4(bb[p ^ 1][jj][0], bb[p ^ 1][jj][1], bb[p ^ 1][jj][2], bb[p ^ 1][jj][3],
                        aj[jj] + (uint32_t)((kc + 1) * 32));
        }

        // prefetch kc+2 W into the parity just consumed
        if (kc + 2 < NK) {
#pragma unroll
            for (int im = 0; im < 2; im++) {
                if (im < nmt) {
                    const float* p0 = wp0[im] + (kc + 2) * 16;
                    const float* p1 = wp1[im] + (kc + 2) * 16;
                    if (even) { we0[im] = *(const float4*)p0; we1[im] = *(const float4*)p1; }
                    else      { wo0[im] = *(const float4*)p0; wo1[im] = *(const float4*)p1; }
                }
            }
        }

#pragma unroll
        for (int im = 0; im < 2; im++) {
            if (im < nmt) {
#pragma unroll
                for (int jj = 0; jj < 2; jj++) {
                    mma16816(acc[im][2 * jj],     ah[im], &bb[p][jj][0]);
                    mma16816(acc[im][2 * jj + 1], ah[im], &bb[p][jj][2]);
                    mma16816(acc[im][2 * jj],     al[im], &bb[p][jj][0]);
                    mma16816(acc[im][2 * jj + 1], al[im], &bb[p][jj][2]);
                }
            }
        }
    }

    if (!FINAL) {
#pragma unroll
        for (int im = 0; im < 2; im++) {
            if (im < nmt) {
                const int o0 = (warp + im * 8) * 16 + group;
                const int o1 = o0 + 8;
                const float bv0 = __ldg(bias + o0);
                const float bv1 = __ldg(bias + o1);
                const uint32_t po0 = permb(o0);
                const uint32_t po1 = permb(o1);
#pragma unroll
                for (int j = 0; j < 4; j++) {
                    const int bc = j * 8 + tig * 2;
                    float v00 = celu01(acc[im][j][0] + bv0);
                    float v01 = celu01(acc[im][j][1] + bv0);
                    float v10 = celu01(acc[im][j][2] + bv1);
                    float v11 = celu01(acc[im][j][3] + bv1);
                    *(__half*)(Yout + (size_t)bc * POUT + po0)       = __float2half_rn(v00);
                    *(__half*)(Yout + (size_t)(bc + 1) * POUT + po0) = __float2half_rn(v01);
                    *(__half*)(Yout + (size_t)bc * POUT + po1)       = __float2half_rn(v10);
                    *(__half*)(Yout + (size_t)(bc + 1) * POUT + po1) = __float2half_rn(v11);
                }
            }
        }
    } else {
        // fused final: s(b) = sum_o w6[o] * celu(acc + bias)
        float s0[4] = {0.f, 0.f, 0.f, 0.f};
        float s1[4] = {0.f, 0.f, 0.f, 0.f};
#pragma unroll
        for (int im = 0; im < 2; im++) {
            if (im < nmt) {
                const int o0 = (warp + im * 8) * 16 + group;
                const int o1 = o0 + 8;
                const float bv0 = __ldg(bias + o0);
                const float bv1 = __ldg(bias + o1);
                const float wv0 = __ldg(w6p + o0);
                const float wv1 = __ldg(w6p + o1);
#pragma unroll
                for (int j = 0; j < 4; j++) {
                    s0[j] += wv0 * celu01(acc[im][j][0] + bv0)
                           + wv1 * celu01(acc[im][j][2] + bv1);
                    s1[j] += wv0 * celu01(acc[im][j][1] + bv0)
                           + wv1 * celu01(acc[im][j][3] + bv1);
                }
            }
        }
        // reduce across the 8 groups (lanes differing in bits 2..4)
#pragma unroll
        for (int j = 0; j < 4; j++) {
#pragma unroll
            for (int m = 4; m <= 16; m <<= 1) {
                s0[j] += __shfl_xor_sync(0xffffffffu, s0[j], m);
                s1[j] += __shfl_xor_sync(0xffffffffu, s1[j], m);
            }
        }
        if (lane < 4) {
#pragma unroll
            for (int j = 0; j < 4; j++) {
                red[(j * 8 + lane * 2) * 8 + warp]     = s0[j];
                red[(j * 8 + lane * 2 + 1) * 8 + warp] = s1[j];
            }
        }
    }
}

__global__ void __launch_bounds__(NTHREADS, 2)
nn_hmma(const float* __restrict__ aev,
        const float* __restrict__ w0, const float* __restrict__ b0,
        const float* __restrict__ w2, const float* __restrict__ b2,
        const float* __restrict__ w4, const float* __restrict__ b4,
        const float* __restrict__ w6, const float* __restrict__ b6)
{
    extern __shared__ char sm[];
    const int tid = threadIdx.x;
    const int am = blockIdx.x >> 1;       // (a, m) pair
    const int nh = blockIdx.x & 1;        // batch half
    const int a  = am >> 3;

    // init X0 from aev: 32 rows [b][k] fp16, k-permuted
#pragma unroll
    for (int it = 0; it < 24; it++) {
        int f = (it * NTHREADS + tid) * 2;
        int bl = f / D_;
        int k = f % D_;
        int b = nh * 32 + bl;
        float2 v = *(const float2*)(aev + ((size_t)b * A_ + a) * D_ + k);
        *(uint32_t*)(sm + X0_OFF + (size_t)bl * P0 + permb(k)) = cvt2h(v.x, v.y);
    }
    __syncthreads();

    layer<D_, O0_, P0, P1, false>(
        w0 + (size_t)am * O0_ * D_, b0 + (size_t)am * O0_,
        sm + X0_OFF, sm + X1_OFF, nullptr, nullptr);
    __syncthreads();

    layer<O0_, O2_, P1, P2, false>(
        w2 + (size_t)am * O2_ * O0_, b2 + (size_t)am * O2_,
        sm + X1_OFF, sm + X0_OFF, nullptr, nullptr);
    __syncthreads();

    layer<O2_, O4_, P2, 0, true>(
        w4 + (size_t)am * O4_ * O2_, b4 + (size_t)am * O4_,
        sm + X0_OFF, nullptr, w6 + (size_t)am * O4_, (float*)(sm + RED_OFF));
    __syncthreads();

    // sum per-warp partials -> g_partial
    if (tid < 32) {
        const float* red = (const float*)(sm + RED_OFF);
        float s = 0.f;
#pragma unroll
        for (int w = 0; w < 8; w++) s += red[tid * 8 + w];
        g_partial[(size_t)(nh * 32 + tid) * (A_ * M_) + am] = s + __ldg(b6 + am);
    }
}

// ---------------- output assembly ----------------
__global__ void reduce_kernel(float* __restrict__ out, int species_first) {
    __shared__ float sh[256];
    const int b = blockIdx.x;
    float s = 0.f;
    for (int i = threadIdx.x; i < A_ * M_; i += 256)
        s += g_partial[(size_t)b * (A_ * M_) + i];
    sh[threadIdx.x] = s;
    __syncthreads();
    for (int st = 128; st > 0; st >>= 1) {
        if (threadIdx.x < st) sh[threadIdx.x] += sh[threadIdx.x + st];
        __syncthreads();
    }
    if (threadIdx.x == 0)
        out[(species_first ? B_ * A_ : 0) + b] = sh[0] / (float)M_;
}

__global__ void species_kernel(const int* __restrict__ sp, float* __restrict__ out) {
    int i = blockIdx.x * 256 + threadIdx.x;
    if (i < B_ * A_) out[i] = (float)sp[i];
}

extern "C" void kernel_launch(void* const* d_in, const int* in_sizes, int n_in,
                              void* d_out, int out_size) {
    const int*   species = (const int*)  d_in[0];
    const float* aev     = (const float*)d_in[1];
    const float* w0      = (const float*)d_in[2];
    const float* b0      = (const float*)d_in[3];
    const float* w2      = (const float*)d_in[4];
    const float* b2      = (const float*)d_in[5];
    const float* w4      = (const float*)d_in[6];
    const float* b4      = (const float*)d_in[7];
    const float* w6      = (const float*)d_in[8];
    const float* b6      = (const float*)d_in[9];
    float* out = (float*)d_out;

    cudaFuncSetAttribute(nn_hmma, cudaFuncAttributeMaxDynamicSharedMemorySize, SMEM_BYTES);

    nn_hmma<<<A_ * M_ * 2, NTHREADS, SMEM_BYTES>>>(aev, w0, b0, w2, b2, w4, b4, w6, b6);

    const int species_first = (out_size >= B_ * A_ + B_) ? 1 : 0;
    if (species_first)
        species_kernel<<<(B_ * A_) / 256, 256>>>(species, out);
    reduce_kernel<<<B_, 256>>>(out, species_first);
}

// round 11
// speedup vs baseline: 1.0399x; 1.0399x over previous
#include <cuda_runtime.h>
#include <cuda_fp16.h>
#include <stdint.h>
#include <math.h>

#define B_   64
#define A_   128
#define M_   8
#define D_   384
#define O0_  256
#define O2_  192
#define O4_  160

// smem pitches (bytes) for X buffers [b][k] fp16: K*2+16 -> conflict-free LDSM rows
#define P0 784     // K=384
#define P1 528     // K=256
#define P2 400     // K=192

#define X0_OFF 0
#define X1_OFF 50176                  // 64*784
#define RED_OFF 83968                 // 50176 + 64*528
#define SMEM_BYTES 88064              // RED_OFF + 64*16*4

#define NTHREADS 512
#define NMT2 10                       // layer-2 m-tiles (O4_/16)

__device__ float g_partial[B_ * A_ * M_];

__device__ __forceinline__ float celu01(float x) {
    return x > 0.f ? x : 0.1f * expm1f(10.f * x);
}

__device__ __forceinline__ uint32_t smem_u32(const void* p) {
    uint32_t a;
    asm("{ .reg .u64 t; cvta.to.shared.u64 t, %1; cvt.u32.u64 %0, t; }" : "=r"(a) : "l"(p));
    return a;
}

// permuted X row byte offset: pair p -> phys pair (p>>1)+(p&1)*4 within 16-col groups.
// B-frag lane t carries logical k (4t,4t+1)/(4t+2,4t+3) -> contiguous float4 W loads.
__device__ __forceinline__ uint32_t permb(int k) {
    int p  = (k >> 1) & 7;
    int pp = (p >> 1) + ((p & 1) << 2);
    return (uint32_t)(((k & ~15) << 1) + (pp << 2) + ((k & 1) << 1));
}

__device__ __forceinline__ uint32_t cvt2h(float x, float y) {
    uint32_t r;
    asm("cvt.rn.f16x2.f32 %0, %1, %2;" : "=r"(r) : "f"(y), "f"(x));
    return r;
}
// W split: fp16 hi + fp16 residual lo (eff ~22 mantissa bits)
__device__ __forceinline__ void split2h(float x, float y, uint32_t& hi, uint32_t& lo) {
    hi = cvt2h(x, y);
    __half2 h = *reinterpret_cast<__half2*>(&hi);
    lo = cvt2h(x - __low2float(h), y - __high2float(h));
}

__device__ __forceinline__ void ldsm_x4(uint32_t& r0, uint32_t& r1, uint32_t& r2, uint32_t& r3,
                                        uint32_t addr) {
    asm volatile("ldmatrix.sync.aligned.m8n8.x4.shared.b16 {%0,%1,%2,%3}, [%4];"
                 : "=r"(r0), "=r"(r1), "=r"(r2), "=r"(r3) : "r"(addr));
}

__device__ __forceinline__ void mma16816(float c[4], const uint32_t a[4], const uint32_t b[2]) {
    asm volatile(
        "mma.sync.aligned.m16n8k16.row.col.f32.f16.f16.f32 "
        "{%0,%1,%2,%3}, {%4,%5,%6,%7}, {%8,%9}, {%0,%1,%2,%3};"
        : "+f"(c[0]), "+f"(c[1]), "+f"(c[2]), "+f"(c[3])
        : "r"(a[0]), "r"(a[1]), "r"(a[2]), "r"(a[3]), "r"(b[0]), "r"(b[1]));
}

// One layer: D[o][b] = celu(W[o][k] X[k][b] + bias).
// 16 warps, warp w owns m-tile w (w < O/16); each warp computes ALL 8 n-tiles.
// W fp32 streamed (contiguous LDG.128, distance-2 parity prefetch), split to fp16
// hi/lo in regs. X single fp16 (permuted); ldsm.x4 covers two n-tiles, B frags
// double-buffered one kc ahead. 2 MMAs per n-tile-kc.
// FINAL fuses the w6 dot into the epilogue (writes red[b][warp]).
template<int K, int O, int PIN, int POUT, bool FINAL>
__device__ __forceinline__ void layer(
    const float* __restrict__ Wg, const float* __restrict__ bias,
    const char* __restrict__ Xin, char* __restrict__ Yout,
    const float* __restrict__ w6p, float* __restrict__ red)
{
    const int lane  = threadIdx.x & 31;
    const int warp  = threadIdx.x >> 5;
    const int group = lane >> 2;
    const int tig   = lane & 3;
    constexpr int NMT = O / 16;
    constexpr int NK  = K / 16;
    if (warp >= NMT) return;

    // B ldmatrix addresses: pair jj covers n-tiles 2jj, 2jj+1.
    const int q = lane >> 3;
    const int rr = lane & 7;
    const uint32_t xbase = smem_u32(Xin);
    uint32_t aj[4];
#pragma unroll
    for (int jj = 0; jj < 4; jj++)
        aj[jj] = xbase + (uint32_t)((jj * 16 + (q >> 1) * 8 + rr) * PIN + (q & 1) * 16);

    float acc[8][4];
#pragma unroll
    for (int j = 0; j < 8; j++)
#pragma unroll
        for (int e = 0; e < 4; e++) acc[j][e] = 0.f;

    const float* wp0 = Wg + (size_t)(warp * 16 + group) * K + tig * 4;
    const float* wp1 = wp0 + 8 * K;

    // W parity double-buffers, prefetch distance 2
    float4 e0, e1, o0v, o1v;
    e0  = *(const float4*)(wp0);
    e1  = *(const float4*)(wp1);
    o0v = *(const float4*)(wp0 + 16);
    o1v = *(const float4*)(wp1 + 16);

    // B software pipeline: bb[parity][jj][4]
    uint32_t bb[2][4][4];
#pragma unroll
    for (int jj = 0; jj < 4; jj++)
        ldsm_x4(bb[0][jj][0], bb[0][jj][1], bb[0][jj][2], bb[0][jj][3], aj[jj]);

#pragma unroll 2
    for (int kc = 0; kc < NK; kc++) {
        const int p = kc & 1;
        const bool even = (p == 0);
        float4 r0 = even ? e0 : o0v;
        float4 r1 = even ? e1 : o1v;

        // split W chunk to fp16 hi/lo fragments
        uint32_t ah[4], al[4];
        split2h(r0.x, r0.y, ah[0], al[0]);
        split2h(r1.x, r1.y, ah[1], al[1]);
        split2h(r0.z, r0.w, ah[2], al[2]);
        split2h(r1.z, r1.w, ah[3], al[3]);

        // prefetch kc+1 B frags into the other parity
        if (kc + 1 < NK) {
#pragma unroll
            for (int jj = 0; jj < 4; jj++)
                ldsm_x4(bb[p ^ 1][jj][0], bb[p ^ 1][jj][1], bb[p ^ 1][jj][2], bb[p ^ 1][jj][3],
                        aj[jj] + (uint32_t)((kc + 1) * 32));
        }

        // prefetch kc+2 W into the parity buffer just consumed
        if (kc + 2 < NK) {
            const float* p0 = wp0 + (kc + 2) * 16;
            const float* p1 = wp1 + (kc + 2) * 16;
            if (even) { e0 = *(const float4*)p0;  e1 = *(const float4*)p1; }
            else      { o0v = *(const float4*)p0; o1v = *(const float4*)p1; }
        }

#pragma unroll
        for (int jj = 0; jj < 4; jj++) {
            mma16816(acc[2 * jj],     ah, &bb[p][jj][0]);
            mma16816(acc[2 * jj + 1], ah, &bb[p][jj][2]);
            mma16816(acc[2 * jj],     al, &bb[p][jj][0]);
            mma16816(acc[2 * jj + 1], al, &bb[p][jj][2]);
        }
    }

    const int o0 = warp * 16 + group;
    const int o1 = o0 + 8;
    const float bv0 = __ldg(bias + o0);
    const float bv1 = __ldg(bias + o1);

    if (!FINAL) {
        const uint32_t po0 = permb(o0);
        const uint32_t po1 = permb(o1);
#pragma unroll
        for (int j = 0; j < 8; j++) {
            const int bc = j * 8 + tig * 2;
            float v00 = celu01(acc[j][0] + bv0);
            float v01 = celu01(acc[j][1] + bv0);
            float v10 = celu01(acc[j][2] + bv1);
            float v11 = celu01(acc[j][3] + bv1);
            *(__half*)(Yout + (size_t)bc * POUT + po0)       = __float2half_rn(v00);
            *(__half*)(Yout + (size_t)(bc + 1) * POUT + po0) = __float2half_rn(v01);
            *(__half*)(Yout + (size_t)bc * POUT + po1)       = __float2half_rn(v10);
            *(__half*)(Yout + (size_t)(bc + 1) * POUT + po1) = __float2half_rn(v11);
        }
    } else {
        // fused final: per n-tile j, s = sum_{o in this warp's m-tile} w6[o]*celu(...)
        const float wv0 = __ldg(w6p + o0);
        const float wv1 = __ldg(w6p + o1);
        float s0[8], s1[8];
#pragma unroll
        for (int j = 0; j < 8; j++) {
            s0[j] = wv0 * celu01(acc[j][0] + bv0) + wv1 * celu01(acc[j][2] + bv1);
            s1[j] = wv0 * celu01(acc[j][1] + bv0) + wv1 * celu01(acc[j][3] + bv1);
        }
        // reduce across the 8 groups (lane bits 2..4)
#pragma unroll
        for (int j = 0; j < 8; j++) {
#pragma unroll
            for (int m = 4; m <= 16; m <<= 1) {
                s0[j] += __shfl_xor_sync(0xffffffffu, s0[j], m);
                s1[j] += __shfl_xor_sync(0xffffffffu, s1[j], m);
            }
        }
        if (lane < 4) {
#pragma unroll
            for (int j = 0; j < 8; j++) {
                red[(j * 8 + lane * 2) * 16 + warp]     = s0[j];
                red[(j * 8 + lane * 2 + 1) * 16 + warp] = s1[j];
            }
        }
    }
}

__global__ void __launch_bounds__(NTHREADS, 1)
nn_hmma(const float* __restrict__ aev,
        const float* __restrict__ w0, const float* __restrict__ b0,
        const float* __restrict__ w2, const float* __restrict__ b2,
        const float* __restrict__ w4, const float* __restrict__ b4,
        const float* __restrict__ w6, const float* __restrict__ b6)
{
    extern __shared__ char sm[];
    const int tid = threadIdx.x;
    const int am = blockIdx.x, a = am >> 3;

    // init X0 from aev: [b][k] fp16, k-permuted
#pragma unroll
    for (int it = 0; it < 24; it++) {
        int f = (it * NTHREADS + tid) * 2;
        int b = f / D_;
        int k = f % D_;
        float2 v = *(const float2*)(aev + ((size_t)b * A_ + a) * D_ + k);
        *(uint32_t*)(sm + X0_OFF + (size_t)b * P0 + permb(k)) = cvt2h(v.x, v.y);
    }
    __syncthreads();

    layer<D_, O0_, P0, P1, false>(
        w0 + (size_t)am * O0_ * D_, b0 + (size_t)am * O0_,
        sm + X0_OFF, sm + X1_OFF, nullptr, nullptr);
    __syncthreads();

    layer<O0_, O2_, P1, P2, false>(
        w2 + (size_t)am * O2_ * O0_, b2 + (size_t)am * O2_,
        sm + X1_OFF, sm + X0_OFF, nullptr, nullptr);
    __syncthreads();

    layer<O2_, O4_, P2, 0, true>(
        w4 + (size_t)am * O4_ * O2_, b4 + (size_t)am * O4_,
        sm + X0_OFF, nullptr, w6 + (size_t)am * O4_, (float*)(sm + RED_OFF));
    __syncthreads();

    // sum per-warp partials (warps 0..NMT2-1) -> g_partial
    if (tid < 64) {
        const float* red = (const float*)(sm + RED_OFF);
        float s = 0.f;
#pragma unroll
        for (int w = 0; w < NMT2; w++) s += red[tid * 16 + w];
        g_partial[(size_t)tid * (A_ * M_) + am] = s + __ldg(b6 + am);
    }
}

// ---------------- output assembly ----------------
__global__ void reduce_kernel(float* __restrict__ out, int species_first) {
    __shared__ float sh[256];
    const int b = blockIdx.x;
    float s = 0.f;
    for (int i = threadIdx.x; i < A_ * M_; i += 256)
        s += g_partial[(size_t)b * (A_ * M_) + i];
    sh[threadIdx.x] = s;
    __syncthreads();
    for (int st = 128; st > 0; st >>= 1) {
        if (threadIdx.x < st) sh[threadIdx.x] += sh[threadIdx.x + st];
        __syncthreads();
    }
    if (threadIdx.x == 0)
        out[(species_first ? B_ * A_ : 0) + b] = sh[0] / (float)M_;
}

__global__ void species_kernel(const int* __restrict__ sp, float* __restrict__ out) {
    int i = blockIdx.x * 256 + threadIdx.x;
    if (i < B_ * A_) out[i] = (float)sp[i];
}

extern "C" void kernel_launch(void* const* d_in, const int* in_sizes, int n_in,
                              void* d_out, int out_size) {
    const int*   species = (const int*)  d_in[0];
    const float* aev     = (const float*)d_in[1];
    const float* w0      = (const float*)d_in[2];
    const float* b0      = (const float*)d_in[3];
    const float* w2      = (const float*)d_in[4];
    const float* b2      = (const float*)d_in[5];
    const float* w4      = (const float*)d_in[6];
    const float* b4      = (const float*)d_in[7];
    const float* w6      = (const float*)d_in[8];
    const float* b6      = (const float*)d_in[9];
    float* out = (float*)d_out;

    cudaFuncSetAttribute(nn_hmma, cudaFuncAttributeMaxDynamicSharedMemorySize, SMEM_BYTES);

    nn_hmma<<<A_ * M_, NTHREADS, SMEM_BYTES>>>(aev, w0, b0, w2, b2, w4, b4, w6, b6);

    const int species_first = (out_size >= B_ * A_ + B_) ? 1 : 0;
    if (species_first)
        species_kernel<<<(B_ * A_) / 256, 256>>>(species, out);
    reduce_kernel<<<B_, 256>>>(out, species_first);
}

// round 12
// speedup vs baseline: 1.1320x; 1.0885x over previous
#include <cuda_runtime.h>
#include <cuda_fp16.h>
#include <stdint.h>
#include <math.h>

#define B_   64
#define A_   128
#define M_   8
#define D_   384
#define O0_  256
#define O2_  192
#define O4_  160

// smem pitches (bytes) for X buffers [b][k] fp16: K*2+16 -> conflict-free LDSM rows
#define P0 784     // K=384
#define P1 528     // K=256
#define P2 400     // K=192

#define X0_OFF 0
#define X1_OFF 50176                  // 64*784
#define RED_OFF 83968                 // + 64*528
#define WRING_OFF 88064               // 16 warps x 4 stages x 1KB
#define SMEM_BYTES (88064 + 65536)

#define NTHREADS 512
#define NMT2 10                       // layer-2 m-tiles (O4_/16)

__device__ float g_partial[B_ * A_ * M_];

__device__ __forceinline__ float celu01(float x) {
    return x > 0.f ? x : 0.1f * expm1f(10.f * x);
}

__device__ __forceinline__ uint32_t smem_u32(const void* p) {
    uint32_t a;
    asm("{ .reg .u64 t; cvta.to.shared.u64 t, %1; cvt.u32.u64 %0, t; }" : "=r"(a) : "l"(p));
    return a;
}

// permuted X row byte offset: pair p -> phys pair (p>>1)+(p&1)*4 within 16-col groups.
// B-frag lane t carries logical k (4t,4t+1)/(4t+2,4t+3) -> contiguous float4 W loads.
__device__ __forceinline__ uint32_t permb(int k) {
    int p  = (k >> 1) & 7;
    int pp = (p >> 1) + ((p & 1) << 2);
    return (uint32_t)(((k & ~15) << 1) + (pp << 2) + ((k & 1) << 1));
}

__device__ __forceinline__ uint32_t cvt2h(float x, float y) {
    uint32_t r;
    asm("cvt.rn.f16x2.f32 %0, %1, %2;" : "=r"(r) : "f"(y), "f"(x));
    return r;
}
// W split: fp16 hi + fp16 residual lo (eff ~22 mantissa bits)
__device__ __forceinline__ void split2h(float x, float y, uint32_t& hi, uint32_t& lo) {
    hi = cvt2h(x, y);
    __half2 h = *reinterpret_cast<__half2*>(&hi);
    lo = cvt2h(x - __low2float(h), y - __high2float(h));
}

__device__ __forceinline__ void ldsm_x4(uint32_t& r0, uint32_t& r1, uint32_t& r2, uint32_t& r3,
                                        uint32_t addr) {
    asm volatile("ldmatrix.sync.aligned.m8n8.x4.shared.b16 {%0,%1,%2,%3}, [%4];"
                 : "=r"(r0), "=r"(r1), "=r"(r2), "=r"(r3) : "r"(addr));
}

__device__ __forceinline__ void mma16816(float c[4], const uint32_t a[4], const uint32_t b[2]) {
    asm volatile(
        "mma.sync.aligned.m16n8k16.row.col.f32.f16.f16.f32 "
        "{%0,%1,%2,%3}, {%4,%5,%6,%7}, {%8,%9}, {%0,%1,%2,%3};"
        : "+f"(c[0]), "+f"(c[1]), "+f"(c[2]), "+f"(c[3])
        : "r"(a[0]), "r"(a[1]), "r"(a[2]), "r"(a[3]), "r"(b[0]), "r"(b[1]));
}

__device__ __forceinline__ void cp_async16(uint32_t dst, const void* src) {
    asm volatile("cp.async.cg.shared.global [%0], [%1], 16;" :: "r"(dst), "l"(src));
}
#define CP_COMMIT() asm volatile("cp.async.commit_group;" ::: "memory")
#define CP_WAIT2()  asm volatile("cp.async.wait_group 2;" ::: "memory")

// One layer: D[o][b] = celu(W[o][k] X[k][b] + bias).
// 16 warps, warp w owns m-tile w (w < O/16); each warp computes ALL 8 n-tiles.
// W streamed via warp-private cp.async ring (4 stages x 1KB, 3 in flight), then
// LDS.128 + fp16 hi/lo split. B frags via ldsm.x4 (2 n-tiles/instr). 2 MMAs per
// n-tile-kc. FINAL fuses the w6 dot into the epilogue.
template<int K, int O, int PIN, int POUT, bool FINAL>
__device__ __forceinline__ void layer(
    const float* __restrict__ Wg, const float* __restrict__ bias,
    const char* __restrict__ Xin, char* __restrict__ Yout,
    const float* __restrict__ w6p, float* __restrict__ red,
    char* __restrict__ smbase)
{
    const int lane  = threadIdx.x & 31;
    const int warp  = threadIdx.x >> 5;
    const int group = lane >> 2;
    const int tig   = lane & 3;
    constexpr int NMT = O / 16;
    constexpr int NK  = K / 16;
    if (warp >= NMT) return;

    // B ldmatrix addresses: pair jj covers n-tiles 2jj, 2jj+1.
    const int q = lane >> 3;
    const int rr = lane & 7;
    const uint32_t xbase = smem_u32(Xin);
    uint32_t aj[4];
#pragma unroll
    for (int jj = 0; jj < 4; jj++)
        aj[jj] = xbase + (uint32_t)((jj * 16 + (q >> 1) * 8 + rr) * PIN + (q & 1) * 16);

    float acc[8][4];
#pragma unroll
    for (int j = 0; j < 8; j++)
#pragma unroll
        for (int e = 0; e < 4; e++) acc[j][e] = 0.f;

    // W cp.async ring: warp-private 4KB (4 stages x 1KB tile of 16 rows x 16 fp32)
    char* wring = smbase + WRING_OFF + warp * 4096;
    const uint32_t wring_u = smem_u32(wring);
    const float* src0 = Wg + (size_t)(warp * 16 + (lane >> 2)) * K + (lane & 3) * 4;
    const float* src1 = src0 + 8 * K;
    const uint32_t dl = (uint32_t)(lane * 16);

    // prologue: stages 0..2 in flight
#pragma unroll
    for (int s = 0; s < 3; s++) {
        uint32_t db = wring_u + s * 1024;
        cp_async16(db + dl,       src0 + s * 16);
        cp_async16(db + 512 + dl, src1 + s * 16);
        CP_COMMIT();
    }

    // consume-side read offsets (conflict-free: 32 distinct 16B chunks per read)
    const uint32_t roff = (uint32_t)((group * 4 + tig) * 16);

#pragma unroll 4
    for (int kc = 0; kc < NK; kc++) {
        CP_WAIT2();
        __syncwarp();
        const char* stg = wring + (kc & 3) * 1024;
        float4 r0 = *(const float4*)(stg + roff);
        float4 r1 = *(const float4*)(stg + 512 + roff);

        // issue stage kc+3, one commit per iteration (keeps group accounting exact)
        if (kc + 3 < NK) {
            uint32_t db = wring_u + ((kc + 3) & 3) * 1024;
            cp_async16(db + dl,       src0 + (kc + 3) * 16);
            cp_async16(db + 512 + dl, src1 + (kc + 3) * 16);
        }
        CP_COMMIT();

        // split W chunk to fp16 hi/lo fragments
        uint32_t ah[4], al[4];
        split2h(r0.x, r0.y, ah[0], al[0]);
        split2h(r1.x, r1.y, ah[1], al[1]);
        split2h(r0.z, r0.w, ah[2], al[2]);
        split2h(r1.z, r1.w, ah[3], al[3]);

        // B fragments: 8 n-tiles via 4 ldsm.x4
        uint32_t bb[4][4];
#pragma unroll
        for (int jj = 0; jj < 4; jj++)
            ldsm_x4(bb[jj][0], bb[jj][1], bb[jj][2], bb[jj][3],
                    aj[jj] + (uint32_t)(kc * 32));

#pragma unroll
        for (int jj = 0; jj < 4; jj++) {
            mma16816(acc[2 * jj],     ah, &bb[jj][0]);
            mma16816(acc[2 * jj + 1], ah, &bb[jj][2]);
            mma16816(acc[2 * jj],     al, &bb[jj][0]);
            mma16816(acc[2 * jj + 1], al, &bb[jj][2]);
        }
    }

    const int o0 = warp * 16 + group;
    const int o1 = o0 + 8;
    const float bv0 = __ldg(bias + o0);
    const float bv1 = __ldg(bias + o1);

    if (!FINAL) {
        const uint32_t po0 = permb(o0);
        const uint32_t po1 = permb(o1);
#pragma unroll
        for (int j = 0; j < 8; j++) {
            const int bc = j * 8 + tig * 2;
            float v00 = celu01(acc[j][0] + bv0);
            float v01 = celu01(acc[j][1] + bv0);
            float v10 = celu01(acc[j][2] + bv1);
            float v11 = celu01(acc[j][3] + bv1);
            *(__half*)(Yout + (size_t)bc * POUT + po0)       = __float2half_rn(v00);
            *(__half*)(Yout + (size_t)(bc + 1) * POUT + po0) = __float2half_rn(v01);
            *(__half*)(Yout + (size_t)bc * POUT + po1)       = __float2half_rn(v10);
            *(__half*)(Yout + (size_t)(bc + 1) * POUT + po1) = __float2half_rn(v11);
        }
    } else {
        // fused final: s(b) = sum over this warp's o of w6[o]*celu(acc+bias)
        const float wv0 = __ldg(w6p + o0);
        const float wv1 = __ldg(w6p + o1);
        float s0[8], s1[8];
#pragma unroll
        for (int j = 0; j < 8; j++) {
            s0[j] = wv0 * celu01(acc[j][0] + bv0) + wv1 * celu01(acc[j][2] + bv1);
            s1[j] = wv0 * celu01(acc[j][1] + bv0) + wv1 * celu01(acc[j][3] + bv1);
        }
#pragma unroll
        for (int j = 0; j < 8; j++) {
#pragma unroll
            for (int m = 4; m <= 16; m <<= 1) {
                s0[j] += __shfl_xor_sync(0xffffffffu, s0[j], m);
                s1[j] += __shfl_xor_sync(0xffffffffu, s1[j], m);
            }
        }
        if (lane < 4) {
#pragma unroll
            for (int j = 0; j < 8; j++) {
                red[(j * 8 + lane * 2) * 16 + warp]     = s0[j];
                red[(j * 8 + lane * 2 + 1) * 16 + warp] = s1[j];
            }
        }
    }
}

__global__ void __launch_bounds__(NTHREADS, 1)
nn_hmma(const float* __restrict__ aev,
        const float* __restrict__ w0, const float* __restrict__ b0,
        const float* __restrict__ w2, const float* __restrict__ b2,
        const float* __restrict__ w4, const float* __restrict__ b4,
        const float* __restrict__ w6, const float* __restrict__ b6)
{
    extern __shared__ char sm[];
    const int tid = threadIdx.x;
    const int am = blockIdx.x, a = am >> 3;

    // init X0 from aev: [b][k] fp16, k-permuted
#pragma unroll
    for (int it = 0; it < 24; it++) {
        int f = (it * NTHREADS + tid) * 2;
        int b = f / D_;
        int k = f % D_;
        float2 v = *(const float2*)(aev + ((size_t)b * A_ + a) * D_ + k);
        *(uint32_t*)(sm + X0_OFF + (size_t)b * P0 + permb(k)) = cvt2h(v.x, v.y);
    }
    __syncthreads();

    layer<D_, O0_, P0, P1, false>(
        w0 + (size_t)am * O0_ * D_, b0 + (size_t)am * O0_,
        sm + X0_OFF, sm + X1_OFF, nullptr, nullptr, sm);
    __syncthreads();

    layer<O0_, O2_, P1, P2, false>(
        w2 + (size_t)am * O2_ * O0_, b2 + (size_t)am * O2_,
        sm + X1_OFF, sm + X0_OFF, nullptr, nullptr, sm);
    __syncthreads();

    layer<O2_, O4_, P2, 0, true>(
        w4 + (size_t)am * O4_ * O2_, b4 + (size_t)am * O4_,
        sm + X0_OFF, nullptr, w6 + (size_t)am * O4_, (float*)(sm + RED_OFF), sm);
    __syncthreads();

    // sum per-warp partials (warps 0..NMT2-1) -> g_partial
    if (tid < 64) {
        const float* red = (const float*)(sm + RED_OFF);
        float s = 0.f;
#pragma unroll
        for (int w = 0; w < NMT2; w++) s += red[tid * 16 + w];
        g_partial[(size_t)tid * (A_ * M_) + am] = s + __ldg(b6 + am);
    }
}

// ---------------- output assembly ----------------
__global__ void reduce_kernel(float* __restrict__ out, int species_first) {
    __shared__ float sh[256];
    const int b = blockIdx.x;
    float s = 0.f;
    for (int i = threadIdx.x; i < A_ * M_; i += 256)
        s += g_partial[(size_t)b * (A_ * M_) + i];
    sh[threadIdx.x] = s;
    __syncthreads();
    for (int st = 128; st > 0; st >>= 1) {
        if (threadIdx.x < st) sh[threadIdx.x] += sh[threadIdx.x + st];
        __syncthreads();
    }
    if (threadIdx.x == 0)
        out[(species_first ? B_ * A_ : 0) + b] = sh[0] / (float)M_;
}

__global__ void species_kernel(const int* __restrict__ sp, float* __restrict__ out) {
    int i = blockIdx.x * 256 + threadIdx.x;
    if (i < B_ * A_) out[i] = (float)sp[i];
}

extern "C" void kernel_launch(void* const* d_in, const int* in_sizes, int n_in,
                              void* d_out, int out_size) {
    const int*   species = (const int*)  d_in[0];
    const float* aev     = (const float*)d_in[1];
    const float* w0      = (const float*)d_in[2];
    const float* b0      = (const float*)d_in[3];
    const float* w2      = (const float*)d_in[4];
    const float* b2      = (const float*)d_in[5];
    const float* w4      = (const float*)d_in[6];
    const float* b4      = (const float*)d_in[7];
    const float* w6      = (const float*)d_in[8];
    const float* b6      = (const float*)d_in[9];
    float* out = (float*)d_out;

    cudaFuncSetAttribute(nn_hmma, cudaFuncAttributeMaxDynamicSharedMemorySize, SMEM_BYTES);

    nn_hmma<<<A_ * M_, NTHREADS, SMEM_BYTES>>>(aev, w0, b0, w2, b2, w4, b4, w6, b6);

    const int species_first = (out_size >= B_ * A_ + B_) ? 1 : 0;
    if (species_first)
        species_kernel<<<(B_ * A_) / 256, 256>>>(species, out);
    reduce_kernel<<<B_, 256>>>(out, species_first);
}